// round 2
// baseline (speedup 1.0000x reference)
#include <cuda_runtime.h>
#include <cuda_bf16.h>
#include <cstdint>
#include <math.h>

// Problem constants
#define BB 2048
#define NN 50000
#define CC 768
#define TK 16
#define NCAND 32
#define NPARTS 25
#define PART 2048
#define NEG_INF __int_as_float(0xff800000)

// Scratch (device globals: no cudaMalloc allowed)
__device__ float g_inv_en[NN];
__device__ float g_pvals[(size_t)BB * NPARTS * TK];
__device__ int   g_pidx [(size_t)BB * NPARTS * TK];
__device__ int   g_cand [(size_t)BB * NCAND];
__device__ int   g_fidx [(size_t)BB * TK];

// ---------------------------------------------------------------------------
// Kernel 0: inverse embedding norms (one warp per row) — fp32 screening only
// ---------------------------------------------------------------------------
__global__ void norm_kernel(const float* __restrict__ E) {
    int w = (blockIdx.x * blockDim.x + threadIdx.x) >> 5;
    int lane = threadIdx.x & 31;
    if (w >= NN) return;
    const float* row = E + (size_t)w * CC;
    float s = 0.f;
    for (int c = lane; c < CC; c += 32) { float v = row[c]; s += v * v; }
    #pragma unroll
    for (int o = 16; o; o >>= 1) s += __shfl_xor_sync(0xffffffffu, s, o);
    if (lane == 0) g_inv_en[w] = 1.0f / sqrtf(s);
}

// ---------------------------------------------------------------------------
// Kernel 1: fused fp32 SGEMM (128x128 tile, Kc=16) + streaming per-row top-16
// grid: (NPARTS, BB/128), 256 threads, each thread computes 8x8 microtile
// ---------------------------------------------------------------------------
#define SMEM_FLOATS (16*128 + 16*128 + 128 + 128*129 + 128*17 + 128)
#define SMEM_INTS   (128*17 + 128)
#define SMEM_BYTES  ((SMEM_FLOATS + SMEM_INTS) * 4)

__global__ void __launch_bounds__(256, 2) gemm_topk_kernel(
    const float* __restrict__ X, const float* __restrict__ E)
{
    extern __shared__ float sm[];
    float* As     = sm;                       // [16][128]  (kk-major)
    float* Bs     = As + 16 * 128;            // [16][128]
    float* sinv   = Bs + 16 * 128;            // [128]
    float* scores = sinv + 128;               // [128][129] padded
    float* tv     = scores + 128 * 129;       // [128][17]  padded
    float* minv   = tv + 128 * 17;            // [128]
    int*   tix    = (int*)(minv + 128);       // [128][17]
    int*   minpos = tix + 128 * 17;           // [128]

    const int tid  = threadIdx.x;
    const int part = blockIdx.x;
    const int m0   = blockIdx.y * 128;
    const int pstart = part * PART;
    const int pend   = min(pstart + PART, NN);

    for (int i = tid; i < 128 * 17; i += 256) { tv[i] = NEG_INF; tix[i] = 0x7fffffff; }
    if (tid < 128) { minv[tid] = NEG_INF; minpos[tid] = 0; }
    __syncthreads();

    const int ty = tid >> 4;
    const int tx = tid & 15;

    for (int n0 = pstart; n0 < pend; n0 += 128) {
        const int ncols = min(128, pend - n0);

        float acc[8][8];
        #pragma unroll
        for (int i = 0; i < 8; i++)
            #pragma unroll
            for (int j = 0; j < 8; j++) acc[i][j] = 0.f;

        for (int kc = 0; kc < CC; kc += 16) {
            #pragma unroll
            for (int l = 0; l < 2; l++) {
                int id  = tid + l * 256;
                int row = id >> 2;
                int seg = id & 3;
                float4 v = *reinterpret_cast<const float4*>(
                    &X[(size_t)(m0 + row) * CC + kc + seg * 4]);
                As[(seg * 4 + 0) * 128 + row] = v.x;
                As[(seg * 4 + 1) * 128 + row] = v.y;
                As[(seg * 4 + 2) * 128 + row] = v.z;
                As[(seg * 4 + 3) * 128 + row] = v.w;
            }
            #pragma unroll
            for (int l = 0; l < 2; l++) {
                int id  = tid + l * 256;
                int row = id >> 2;
                int seg = id & 3;
                int n   = n0 + row;
                float4 v = make_float4(0.f, 0.f, 0.f, 0.f);
                if (n < pend)
                    v = *reinterpret_cast<const float4*>(
                        &E[(size_t)n * CC + kc + seg * 4]);
                Bs[(seg * 4 + 0) * 128 + row] = v.x;
                Bs[(seg * 4 + 1) * 128 + row] = v.y;
                Bs[(seg * 4 + 2) * 128 + row] = v.z;
                Bs[(seg * 4 + 3) * 128 + row] = v.w;
            }
            __syncthreads();

            #pragma unroll
            for (int kk = 0; kk < 16; kk++) {
                float a[8], b[8];
                *reinterpret_cast<float4*>(&a[0]) =
                    *reinterpret_cast<const float4*>(&As[kk * 128 + ty * 8]);
                *reinterpret_cast<float4*>(&a[4]) =
                    *reinterpret_cast<const float4*>(&As[kk * 128 + ty * 8 + 4]);
                *reinterpret_cast<float4*>(&b[0]) =
                    *reinterpret_cast<const float4*>(&Bs[kk * 128 + tx * 8]);
                *reinterpret_cast<float4*>(&b[4]) =
                    *reinterpret_cast<const float4*>(&Bs[kk * 128 + tx * 8 + 4]);
                #pragma unroll
                for (int i = 0; i < 8; i++)
                    #pragma unroll
                    for (int j = 0; j < 8; j++)
                        acc[i][j] = fmaf(a[i], b[j], acc[i][j]);
            }
            __syncthreads();
        }

        #pragma unroll
        for (int i = 0; i < 8; i++)
            #pragma unroll
            for (int j = 0; j < 8; j++)
                scores[(ty * 8 + i) * 129 + tx * 8 + j] = acc[i][j];
        if (tid < 128) {
            int n = n0 + tid;
            sinv[tid] = (n < pend) ? g_inv_en[n] : 0.f;
        }
        __syncthreads();

        if (tid < 128) {
            const int r = tid;
            float mv = minv[r];
            int   mp = minpos[r];
            for (int c = 0; c < ncols; c++) {
                float s = scores[r * 129 + c] * sinv[c];
                if (s > mv) {
                    tv[r * 17 + mp]  = s;
                    tix[r * 17 + mp] = n0 + c;
                    mv = tv[r * 17]; mp = 0; int mi = tix[r * 17];
                    #pragma unroll
                    for (int q = 1; q < TK; q++) {
                        float v  = tv[r * 17 + q];
                        int   iq = tix[r * 17 + q];
                        if (v < mv || (v == mv && iq > mi)) { mv = v; mp = q; mi = iq; }
                    }
                }
            }
            minv[r] = mv; minpos[r] = mp;
        }
        __syncthreads();
    }

    if (tid < 128) {
        const int b = m0 + tid;
        const size_t base = ((size_t)b * NPARTS + part) * TK;
        #pragma unroll
        for (int q = 0; q < TK; q++) {
            g_pvals[base + q] = tv[tid * 17 + q];
            g_pidx [base + q] = tix[tid * 17 + q];
        }
    }
}

// ---------------------------------------------------------------------------
// Kernel 2: merge 25x16 partials -> fp32 top-32 candidate pool per row
// one warp per row; ties: value desc primary, index asc secondary
// ---------------------------------------------------------------------------
__global__ void merge_kernel() {
    const int warp = threadIdx.x >> 5;
    const int lane = threadIdx.x & 31;
    const int row  = blockIdx.x * 8 + warp;
    if (row >= BB) return;

    const int NC = NPARTS * TK;   // 400
    float lv[13];
    int   li[13];
    #pragma unroll
    for (int t = 0; t < 13; t++) {
        int g = lane + t * 32;
        if (g < NC) {
            lv[t] = g_pvals[(size_t)row * NC + g];
            li[t] = g_pidx [(size_t)row * NC + g];
        } else { lv[t] = NEG_INF; li[t] = 0x7fffffff; }
    }

    for (int rnd = 0; rnd < NCAND; rnd++) {
        float bv = NEG_INF; int bi = 0x7fffffff; int bs = -1;
        #pragma unroll
        for (int t = 0; t < 13; t++) {
            if (lv[t] > bv || (lv[t] == bv && li[t] < bi)) { bv = lv[t]; bi = li[t]; bs = t; }
        }
        float wv = bv; int wi = bi;
        #pragma unroll
        for (int o = 16; o; o >>= 1) {
            float ov = __shfl_xor_sync(0xffffffffu, wv, o);
            int   oi = __shfl_xor_sync(0xffffffffu, wi, o);
            if (ov > wv || (ov == wv && oi < wi)) { wv = ov; wi = oi; }
        }
        if (bs >= 0 && bv == wv && bi == wi) { lv[bs] = NEG_INF; li[bs] = 0x7fffffff; }
        if (lane == 0) g_cand[row * NCAND + rnd] = wi;
    }
}

// ---------------------------------------------------------------------------
// Kernel 2.5: fp64 refinement — exact re-ranking of the 32 candidates/row.
// One warp per row, lane = candidate. dot and ||e||^2 fused in one pass.
// ---------------------------------------------------------------------------
__global__ void refine_kernel(const float* __restrict__ X, const float* __restrict__ E) {
    const int warp = threadIdx.x >> 5;
    const int lane = threadIdx.x & 31;
    const int row  = blockIdx.x * 8 + warp;
    if (row >= BB) return;

    const int cand = g_cand[row * NCAND + lane];
    const float4* x4 = reinterpret_cast<const float4*>(X + (size_t)row  * CC);
    const float4* e4 = reinterpret_cast<const float4*>(E + (size_t)cand * CC);

    double dot = 0.0, e2 = 0.0;
    #pragma unroll 4
    for (int c = 0; c < CC / 4; c++) {
        float4 xv = x4[c];
        float4 ev = e4[c];
        dot = fma((double)xv.x, (double)ev.x, dot);
        dot = fma((double)xv.y, (double)ev.y, dot);
        dot = fma((double)xv.z, (double)ev.z, dot);
        dot = fma((double)xv.w, (double)ev.w, dot);
        e2  = fma((double)ev.x, (double)ev.x, e2);
        e2  = fma((double)ev.y, (double)ev.y, e2);
        e2  = fma((double)ev.z, (double)ev.z, e2);
        e2  = fma((double)ev.w, (double)ev.w, e2);
    }
    double sim = dot / sqrt(e2);   // per-row 1/||x|| factor is rank-invariant

    double v = sim;
    int idx = cand;
    for (int rnd = 0; rnd < TK; rnd++) {
        double wv = v; int wi = idx;
        #pragma unroll
        for (int o = 16; o; o >>= 1) {
            double ov = __shfl_xor_sync(0xffffffffu, wv, o);
            int    oi = __shfl_xor_sync(0xffffffffu, wi, o);
            if (ov > wv || (ov == wv && oi < wi)) { wv = ov; wi = oi; }
        }
        if (idx == wi) { v = -INFINITY; idx = 0x7fffffff; }  // indices unique
        if (lane == 0) g_fidx[row * TK + rnd] = wi;
    }
}

// ---------------------------------------------------------------------------
// Kernel 3: gather with the reference's reshape(-1,B,C).transpose(1,0,2)
// scramble:  out[b][j] = E[ fidx[j*128 + b/16][b%16] ]
// ---------------------------------------------------------------------------
__global__ void gather_kernel(const float* __restrict__ E, float* __restrict__ out) {
    const int bj = blockIdx.x;        // b*16 + j
    const int b = bj >> 4, j = bj & 15;
    const int src_row  = j * (BB / TK) + (b >> 4);   // j*128 + b/16
    const int src_slot = b & 15;
    const int src = g_fidx[src_row * TK + src_slot];
    const float4* s4 = reinterpret_cast<const float4*>(E + (size_t)src * CC);
    float4* d4 = reinterpret_cast<float4*>(out + (size_t)bj * CC);
    d4[threadIdx.x] = s4[threadIdx.x];    // 192 threads x float4 = 768 floats
}

// ---------------------------------------------------------------------------
extern "C" void kernel_launch(void* const* d_in, const int* in_sizes, int n_in,
                              void* d_out, int out_size) {
    const float* X = (const float*)d_in[0];
    const float* E = (const float*)d_in[1];
    float* out = (float*)d_out;
    (void)in_sizes; (void)n_in; (void)out_size;

    cudaFuncSetAttribute(gemm_topk_kernel,
                         cudaFuncAttributeMaxDynamicSharedMemorySize, SMEM_BYTES);

    norm_kernel<<<NN / 8, 256>>>(E);
    gemm_topk_kernel<<<dim3(NPARTS, BB / 128), 256, SMEM_BYTES>>>(X, E);
    merge_kernel<<<BB / 8, 256>>>();
    refine_kernel<<<BB / 8, 256>>>(X, E);
    gather_kernel<<<BB * TK, 192>>>(E, out);
}

// round 4
// speedup vs baseline: 2.7947x; 2.7947x over previous
#include <cuda_runtime.h>
#include <cuda_bf16.h>
#include <cstdint>
#include <math.h>

// ---------------------------------------------------------------------------
// Problem constants
#define BB 2048
#define NN 50000
#define CC 768
#define TK 16
#define NCAND 32
#define NPARTS 37
#define NT 11                 // 128-col tiles per part
#define PSPAN (NT*128)        // 1408
#define NPAD (NPARTS*PSPAN)   // 52096
#define NLISTS (2*NPARTS)     // 74 partial lists per row (2 col-halves per part)
#define NEG_INF __int_as_float(0xff800000)

// Scratch (device globals: no cudaMalloc allowed)
__device__ __nv_bfloat16 g_Ebf[(size_t)NPAD * CC];   // row-scaled by 1/||e||
__device__ __nv_bfloat16 g_Xbf[(size_t)BB * CC];
__device__ float  g_pvals[(size_t)BB * NLISTS * TK];
__device__ int    g_pidx [(size_t)BB * NLISTS * TK];
__device__ int    g_cand [(size_t)BB * NCAND];
__device__ double g_csim [(size_t)BB * NCAND];
__device__ int    g_fidx [(size_t)BB * TK];

// ---------------------------------------------------------------------------
// Baseline-PTX helpers (NO sm_103a-gated instructions)
// ---------------------------------------------------------------------------
__device__ __forceinline__ uint32_t smem_u32(const void* p) {
    uint32_t a;
    asm("{ .reg .u64 t; cvta.to.shared.u64 t, %1; cvt.u32.u64 %0, t; }" : "=r"(a) : "l"(p));
    return a;
}
__device__ __forceinline__ void cp16(uint32_t saddr, const void* g) {
    asm volatile("cp.async.cg.shared.global [%0], [%1], 16;" :: "r"(saddr), "l"(g));
}
#define CP_COMMIT() asm volatile("cp.async.commit_group;" ::: "memory")
#define CP_WAIT0()  asm volatile("cp.async.wait_group 0;" ::: "memory")
#define CP_WAIT1()  asm volatile("cp.async.wait_group 1;" ::: "memory")

__device__ __forceinline__ void ldm_x4(uint32_t& r0, uint32_t& r1, uint32_t& r2,
                                       uint32_t& r3, uint32_t a) {
    asm volatile("ldmatrix.sync.aligned.m8n8.x4.shared.b16 {%0,%1,%2,%3}, [%4];"
                 : "=r"(r0), "=r"(r1), "=r"(r2), "=r"(r3) : "r"(a));
}
__device__ __forceinline__ void mma16816(float* c, const uint32_t* a, const uint32_t* b) {
    asm volatile(
        "mma.sync.aligned.m16n8k16.row.col.f32.bf16.bf16.f32 "
        "{%0,%1,%2,%3}, {%4,%5,%6,%7}, {%8,%9}, {%0,%1,%2,%3};"
        : "+f"(c[0]), "+f"(c[1]), "+f"(c[2]), "+f"(c[3])
        : "r"(a[0]), "r"(a[1]), "r"(a[2]), "r"(a[3]), "r"(b[0]), "r"(b[1]));
}
__device__ __forceinline__ uint32_t swz(uint32_t off) { return off ^ ((off >> 3) & 0x70); }

// ---------------------------------------------------------------------------
// Prepass: E -> bf16 scaled by 1/||e|| (rows >= NN zeroed); X -> bf16
// ---------------------------------------------------------------------------
__global__ void prepE_kernel(const float* __restrict__ E) {
    int w = (blockIdx.x * blockDim.x + threadIdx.x) >> 5;
    int lane = threadIdx.x & 31;
    if (w >= NPAD) return;
    uint32_t* orow = reinterpret_cast<uint32_t*>(g_Ebf + (size_t)w * CC);
    if (w >= NN) {
        #pragma unroll
        for (int i = 0; i < 6; i++) { orow[(lane+32*i)*2] = 0u; orow[(lane+32*i)*2+1] = 0u; }
        return;
    }
    const float4* r4 = reinterpret_cast<const float4*>(E + (size_t)w * CC);
    float s = 0.f;
    float4 v[6];
    #pragma unroll
    for (int i = 0; i < 6; i++) {
        v[i] = r4[lane + 32*i];
        s += v[i].x*v[i].x + v[i].y*v[i].y + v[i].z*v[i].z + v[i].w*v[i].w;
    }
    #pragma unroll
    for (int o = 16; o; o >>= 1) s += __shfl_xor_sync(0xffffffffu, s, o);
    float inv = rsqrtf(s);
    #pragma unroll
    for (int i = 0; i < 6; i++) {
        __nv_bfloat162 h0 = __floats2bfloat162_rn(v[i].x*inv, v[i].y*inv);
        __nv_bfloat162 h1 = __floats2bfloat162_rn(v[i].z*inv, v[i].w*inv);
        orow[(lane+32*i)*2]   = *reinterpret_cast<uint32_t*>(&h0);
        orow[(lane+32*i)*2+1] = *reinterpret_cast<uint32_t*>(&h1);
    }
}

__global__ void prepX_kernel(const float* __restrict__ X) {
    int w = (blockIdx.x * blockDim.x + threadIdx.x) >> 5;
    int lane = threadIdx.x & 31;
    if (w >= BB) return;
    const float4* r4 = reinterpret_cast<const float4*>(X + (size_t)w * CC);
    uint32_t* orow = reinterpret_cast<uint32_t*>(g_Xbf + (size_t)w * CC);
    #pragma unroll
    for (int i = 0; i < 6; i++) {
        float4 v = r4[lane + 32*i];
        __nv_bfloat162 h0 = __floats2bfloat162_rn(v.x, v.y);
        __nv_bfloat162 h1 = __floats2bfloat162_rn(v.z, v.w);
        orow[(lane+32*i)*2]   = *reinterpret_cast<uint32_t*>(&h0);
        orow[(lane+32*i)*2+1] = *reinterpret_cast<uint32_t*>(&h1);
    }
}

// ---------------------------------------------------------------------------
// Kernel 1: bf16 HMMA GEMM (mma.sync m16n8k16) + streaming per-row top-16.
// 128x128 CTA tile, 8 warps (2M x 4N), warp tile 64x32, K-chunk 64.
// cp.async double-buffered stages; epilogue via smem scores (pitch 133).
// grid(16 Mblk, 37 parts), 256 threads.
// ---------------------------------------------------------------------------
#define STAGE_BYTES 32768              // A 16KB + B 16KB
#define SC_OFF      65536              // scores after 2 stages
#define SC_PITCH    133
#define GSMEM       (SC_OFF + 128*SC_PITCH*4)   // 133,632 B

__global__ void __launch_bounds__(256, 1) gemm_topk_kernel() {
    extern __shared__ char sm[];
    const uint32_t smb = smem_u32(sm);
    float* scores = reinterpret_cast<float*>(sm + SC_OFF);

    const int tid  = threadIdx.x;
    const int warp = tid >> 5;
    const int lane = tid & 31;
    const int m0   = blockIdx.x * 128;
    const int part = blockIdx.y;
    const int pbase = part * PSPAN;

    const int wm = warp & 1;        // 2 M-warps (64 rows each)
    const int wn = warp >> 1;       // 4 N-warps (32 cols each)

    // issue one 32KB stage (A chunk + B chunk) via cp.async
    auto issue = [&](int ci, int stage) {
        const int t = ci / 12, c = ci % 12;
        const uint32_t as = smb + stage * STAGE_BYTES;
        const uint32_t bs = as + 16384;
        const __nv_bfloat16* Ab = g_Xbf + (size_t)m0 * CC + c * 64;
        const __nv_bfloat16* Bb = g_Ebf + (size_t)(pbase + t * 128) * CC + c * 64;
        #pragma unroll
        for (int s = 0; s < 4; s++) {
            int u = tid + 256 * s;          // 0..1023
            int row = u >> 3, seg = u & 7;
            cp16(as + swz(row * 128 + seg * 16), Ab + (size_t)row * CC + seg * 8);
            cp16(bs + swz(row * 128 + seg * 16), Bb + (size_t)row * CC + seg * 8);
        }
        CP_COMMIT();
    };

    // per-(row,half) streaming top-16 (thread tid: row=tid&127, half=tid>>7)
    float tvv[TK]; int tii[TK];
    #pragma unroll
    for (int q = 0; q < TK; q++) { tvv[q] = NEG_INF; tii[q] = 0x7fffffff; }
    float mv = NEG_INF; int mp = 0;

    float acc[4][4][4];
    #pragma unroll
    for (int i = 0; i < 4; i++)
        #pragma unroll
        for (int j = 0; j < 4; j++)
            #pragma unroll
            for (int r = 0; r < 4; r++) acc[i][j][r] = 0.f;

    // precomputed ldmatrix lane-address components
    const int a_row = (lane & 15);
    const int a_kh  = (lane >> 4) & 1;
    const int b_nrw = ((lane >> 4) & 1) * 8 + (lane & 7);
    const int b_kh  = (lane >> 3) & 1;

    issue(0, 0);

    const int NCHUNK = NT * 12;   // 132
    for (int ci = 0; ci < NCHUNK; ci++) {
        if (ci + 1 < NCHUNK) { issue(ci + 1, (ci + 1) & 1); CP_WAIT1(); }
        else                 { CP_WAIT0(); }
        __syncthreads();

        // compute chunk ci from stage ci&1
        {
            const uint32_t as = smb + (ci & 1) * STAGE_BYTES;
            const uint32_t bs = as + 16384;
            #pragma unroll
            for (int ks = 0; ks < 4; ks++) {
                uint32_t a[4][4], b[2][4];
                #pragma unroll
                for (int i = 0; i < 4; i++) {
                    uint32_t off = (uint32_t)(wm * 64 + i * 16 + a_row) * 128
                                 + ks * 32 + a_kh * 16;
                    ldm_x4(a[i][0], a[i][1], a[i][2], a[i][3], as + swz(off));
                }
                #pragma unroll
                for (int j16 = 0; j16 < 2; j16++) {
                    uint32_t off = (uint32_t)(wn * 32 + j16 * 16 + b_nrw) * 128
                                 + ks * 32 + b_kh * 16;
                    ldm_x4(b[j16][0], b[j16][1], b[j16][2], b[j16][3], bs + swz(off));
                }
                #pragma unroll
                for (int i = 0; i < 4; i++)
                    #pragma unroll
                    for (int j2 = 0; j2 < 4; j2++)
                        mma16816(acc[i][j2], a[i], &b[j2 >> 1][(j2 & 1) * 2]);
            }
        }

        if ((ci % 12) == 11) {
            // tile epilogue: stage scores then scan
            const int t = ci / 12;
            const int n0 = pbase + t * 128;
            __syncthreads();   // previous scan fully done (scores reuse)
            #pragma unroll
            for (int i = 0; i < 4; i++) {
                int row = wm * 64 + i * 16 + (lane >> 2);
                #pragma unroll
                for (int j2 = 0; j2 < 4; j2++) {
                    int col = wn * 32 + j2 * 8 + (lane & 3) * 2;
                    scores[row * SC_PITCH + col]           = acc[i][j2][0];
                    scores[row * SC_PITCH + col + 1]       = acc[i][j2][1];
                    scores[(row + 8) * SC_PITCH + col]     = acc[i][j2][2];
                    scores[(row + 8) * SC_PITCH + col + 1] = acc[i][j2][3];
                    acc[i][j2][0] = 0.f; acc[i][j2][1] = 0.f;
                    acc[i][j2][2] = 0.f; acc[i][j2][3] = 0.f;
                }
            }
            __syncthreads();
            {
                const int r    = tid & 127;
                const int half = tid >> 7;
                const float* srow = scores + r * SC_PITCH + half * 64;
                for (int c2 = 0; c2 < 64; c2++) {
                    int n = n0 + half * 64 + c2;
                    float s = srow[c2];
                    if (n < NN && s > mv) {
                        #pragma unroll
                        for (int q = 0; q < TK; q++)
                            if (q == mp) { tvv[q] = s; tii[q] = n; }
                        mv = tvv[0]; mp = 0; int mi = tii[0];
                        #pragma unroll
                        for (int q = 1; q < TK; q++) {
                            if (tvv[q] < mv || (tvv[q] == mv && tii[q] > mi)) {
                                mv = tvv[q]; mp = q; mi = tii[q];
                            }
                        }
                    }
                }
            }
        }
        __syncthreads();   // stage buffer safe to overwrite next iteration
    }

    // dump candidate lists: list id = part*2 + half
    {
        const int b = m0 + (tid & 127);
        const int list = part * 2 + (tid >> 7);
        const size_t base = ((size_t)b * NLISTS + list) * TK;
        #pragma unroll
        for (int q = 0; q < TK; q++) { g_pvals[base + q] = tvv[q]; g_pidx[base + q] = tii[q]; }
    }
}

// ---------------------------------------------------------------------------
// Kernel 2: merge 74x16 partials -> top-32 candidate pool per row (warp/row)
// ---------------------------------------------------------------------------
__global__ void merge_kernel() {
    const int warp = threadIdx.x >> 5;
    const int lane = threadIdx.x & 31;
    const int row  = blockIdx.x * 8 + warp;
    if (row >= BB) return;

    const int NC = NLISTS * TK;   // 1184
    const int T = NC / 32;        // 37
    float lv[T]; int li[T];
    #pragma unroll
    for (int t = 0; t < T; t++) {
        int g = lane + t * 32;
        lv[t] = g_pvals[(size_t)row * NC + g];
        li[t] = g_pidx [(size_t)row * NC + g];
    }
    for (int rnd = 0; rnd < NCAND; rnd++) {
        float bv = NEG_INF; int bi = 0x7fffffff; int bs = -1;
        #pragma unroll
        for (int t = 0; t < T; t++)
            if (lv[t] > bv || (lv[t] == bv && li[t] < bi)) { bv = lv[t]; bi = li[t]; bs = t; }
        float wv = bv; int wi = bi;
        #pragma unroll
        for (int o = 16; o; o >>= 1) {
            float ov = __shfl_xor_sync(0xffffffffu, wv, o);
            int   oi = __shfl_xor_sync(0xffffffffu, wi, o);
            if (ov > wv || (ov == wv && oi < wi)) { wv = ov; wi = oi; }
        }
        if (bs >= 0 && bv == wv && bi == wi) { lv[bs] = NEG_INF; li[bs] = 0x7fffffff; }
        if (lane == 0) g_cand[row * NCAND + rnd] = wi;
    }
}

// ---------------------------------------------------------------------------
// Kernel 2.5a: fp64 exact sims — one WARP per (row, candidate)
// ---------------------------------------------------------------------------
__global__ void refine_dot_kernel(const float* __restrict__ X, const float* __restrict__ E) {
    const int gw   = blockIdx.x * 8 + (threadIdx.x >> 5);
    const int lane = threadIdx.x & 31;
    const int row  = gw >> 5;
    const int slot = gw & 31;
    if (row >= BB) return;
    const int cand = g_cand[row * NCAND + slot];
    const float4* x4 = reinterpret_cast<const float4*>(X + (size_t)row  * CC);
    const float4* e4 = reinterpret_cast<const float4*>(E + (size_t)cand * CC);

    double dot = 0.0, e2 = 0.0;
    #pragma unroll
    for (int i = 0; i < 6; i++) {
        float4 xv = x4[lane + 32 * i];
        float4 ev = e4[lane + 32 * i];
        dot = fma((double)xv.x, (double)ev.x, dot);
        e2  = fma((double)ev.x, (double)ev.x, e2);
        dot = fma((double)xv.y, (double)ev.y, dot);
        e2  = fma((double)ev.y, (double)ev.y, e2);
        dot = fma((double)xv.z, (double)ev.z, dot);
        e2  = fma((double)ev.z, (double)ev.z, e2);
        dot = fma((double)xv.w, (double)ev.w, dot);
        e2  = fma((double)ev.w, (double)ev.w, e2);
    }
    #pragma unroll
    for (int o = 16; o; o >>= 1) {
        dot += __shfl_xor_sync(0xffffffffu, dot, o);
        e2  += __shfl_xor_sync(0xffffffffu, e2,  o);
    }
    if (lane == 0) g_csim[row * NCAND + slot] = dot / sqrt(e2);
}

// Kernel 2.5b: sorted top-16 of the 32 exact sims (warp per row)
__global__ void refine_select_kernel() {
    const int warp = threadIdx.x >> 5;
    const int lane = threadIdx.x & 31;
    const int row  = blockIdx.x * 8 + warp;
    if (row >= BB) return;

    double v = g_csim[row * NCAND + lane];
    int  idx = g_cand[row * NCAND + lane];
    for (int rnd = 0; rnd < TK; rnd++) {
        double wv = v; int wi = idx;
        #pragma unroll
        for (int o = 16; o; o >>= 1) {
            double ov = __shfl_xor_sync(0xffffffffu, wv, o);
            int    oi = __shfl_xor_sync(0xffffffffu, wi, o);
            if (ov > wv || (ov == wv && oi < wi)) { wv = ov; wi = oi; }
        }
        if (idx == wi) { v = -INFINITY; idx = 0x7fffffff; }
        if (lane == 0) g_fidx[row * TK + rnd] = wi;
    }
}

// ---------------------------------------------------------------------------
// Kernel 3: gather with reference's reshape(-1,B,C).transpose(1,0,2) scramble
// ---------------------------------------------------------------------------
__global__ void gather_kernel(const float* __restrict__ E, float* __restrict__ out) {
    const int bj = blockIdx.x;        // b*16 + j
    const int b = bj >> 4, j = bj & 15;
    const int src_row  = j * (BB / TK) + (b >> 4);
    const int src_slot = b & 15;
    const int src = g_fidx[src_row * TK + src_slot];
    const float4* s4 = reinterpret_cast<const float4*>(E + (size_t)src * CC);
    float4* d4 = reinterpret_cast<float4*>(out + (size_t)bj * CC);
    d4[threadIdx.x] = s4[threadIdx.x];
}

// ---------------------------------------------------------------------------
extern "C" void kernel_launch(void* const* d_in, const int* in_sizes, int n_in,
                              void* d_out, int out_size) {
    const float* X = (const float*)d_in[0];
    const float* E = (const float*)d_in[1];
    float* out = (float*)d_out;
    (void)in_sizes; (void)n_in; (void)out_size;

    cudaFuncSetAttribute(gemm_topk_kernel,
                         cudaFuncAttributeMaxDynamicSharedMemorySize, GSMEM);

    prepE_kernel<<<NPAD / 8, 256>>>(E);
    prepX_kernel<<<BB / 8, 256>>>(X);
    gemm_topk_kernel<<<dim3(16, NPARTS), 256, GSMEM>>>();
    merge_kernel<<<BB / 8, 256>>>();
    refine_dot_kernel<<<BB * NCAND / 8, 256>>>(X, E);
    refine_select_kernel<<<BB / 8, 256>>>();
    gather_kernel<<<BB * TK, 192>>>(E, out);
}